// round 5
// baseline (speedup 1.0000x reference)
#include <cuda_runtime.h>
#include <cstdint>

// Problem constants
#define Bq   64
#define Kk   4096
#define Dd   512
#define Hh   512

// Scratch (no cudaMalloc allowed)
__device__ float g_qh[Bq * Hh];
__device__ float g_kh[Kk * Hh];

// ---------------------------------------------------------------------------
// f32x2 packed helpers
// ---------------------------------------------------------------------------
__device__ __forceinline__ unsigned long long pack2(float x, float y) {
    unsigned long long r;
    asm("mov.b64 %0, {%1, %2};" : "=l"(r) : "r"(__float_as_uint(x)), "r"(__float_as_uint(y)));
    return r;
}
__device__ __forceinline__ void fma2(unsigned long long& d,
                                     unsigned long long a, unsigned long long b) {
    asm("fma.rn.f32x2 %0, %1, %2, %0;" : "+l"(d) : "l"(a), "l"(b));
}
__device__ __forceinline__ unsigned long long add2(unsigned long long a,
                                                   unsigned long long b) {
    unsigned long long r;
    asm("add.rn.f32x2 %0, %1, %2;" : "=l"(r) : "l"(a), "l"(b));
    return r;
}
__device__ __forceinline__ float2 unpack2(unsigned long long v) {
    unsigned int lo, hi;
    asm("mov.b64 {%0, %1}, %2;" : "=r"(lo), "=r"(hi) : "l"(v));
    return make_float2(__uint_as_float(lo), __uint_as_float(hi));
}

// ---------------------------------------------------------------------------
// Fused kernel:
//   blocks [0,256)   : kh' = key_embed @ W1[D:] + b1   (64x128 tiles)
//   blocks [256,288) : qh  = gather(query_embed) @ W1[:D]
// ---------------------------------------------------------------------------
#define TBM 64
#define TBN 128
#define TBK 8
#define APITCH 68   // pad: keeps LDS.128 16B-aligned (68*4=272) + conflict-free stores

__global__ __launch_bounds__(256) void fused_qh_kh(const int* __restrict__ Xq,
                                                   const float* __restrict__ qemb,
                                                   const float* __restrict__ kemb,
                                                   const float* __restrict__ W1,
                                                   const float* __restrict__ b1) {
    __shared__ union {
        struct { float As[TBK][APITCH]; float Bs[TBK][TBN]; } g;  // ~6.2 KB
        float qs[Dd][4];                                           // 8 KB
    } sm;

    int t = threadIdx.x;

    if (blockIdx.x < 256) {
        // ------------------- kh role: 64m x 128n tile GEMM + b1 ----------------
        const float* A  = kemb;
        const float* Bm = W1 + (size_t)Dd * Hh;    // W1[D:, :]

        int tx  = t & 15;                // n (16) -> 8 cols per thread
        int ty  = t >> 4;                // m (16) -> 4 rows per thread
        int bn0 = (blockIdx.x & 3) * TBN;
        int bm0 = (blockIdx.x >> 2) * TBM;

        // A tile 64x8 = 512 floats: threads [0,128) load 1 float4 each
        int arow = t >> 1;               // 0..63 (t<128)
        int acol = (t & 1) * 4;          // 0 or 4
        // B tile 8x128 = 1024 floats: all 256 threads load 1 float4 each
        int brow = t >> 5;               // 0..7
        int bcol = (t & 31) * 4;         // 0..124

        const float* Aptr = A  + (size_t)(bm0 + arow) * Dd + acol;
        const float* Bptr = Bm + (size_t)brow * Hh + bn0 + bcol;

        unsigned long long acc[4][4];
#pragma unroll
        for (int i = 0; i < 4; ++i)
#pragma unroll
            for (int p = 0; p < 4; ++p) acc[i][p] = 0ULL;

        float4 a4 = (t < 128) ? *(const float4*)Aptr : make_float4(0, 0, 0, 0);
        float4 b4 = *(const float4*)Bptr;

        for (int kc = 0; kc < Dd; kc += TBK) {
            if (t < 128) {
                sm.g.As[acol + 0][arow] = a4.x;
                sm.g.As[acol + 1][arow] = a4.y;
                sm.g.As[acol + 2][arow] = a4.z;
                sm.g.As[acol + 3][arow] = a4.w;
            }
            *(float4*)&sm.g.Bs[brow][bcol] = b4;
            __syncthreads();

            if (kc + TBK < Dd) {
                if (t < 128) a4 = *(const float4*)(Aptr + kc + TBK);
                b4 = *(const float4*)(Bptr + (size_t)(kc + TBK) * Hh);
            }

#pragma unroll
            for (int d = 0; d < TBK; ++d) {
                float a[4];
                *(float4*)&a[0] = *(const float4*)&sm.g.As[d][4 * ty];
                unsigned long long bb[4];
                bb[0] = *(const unsigned long long*)&sm.g.Bs[d][4 * tx];
                bb[1] = *(const unsigned long long*)&sm.g.Bs[d][4 * tx + 2];
                bb[2] = *(const unsigned long long*)&sm.g.Bs[d][64 + 4 * tx];
                bb[3] = *(const unsigned long long*)&sm.g.Bs[d][64 + 4 * tx + 2];
#pragma unroll
                for (int i = 0; i < 4; ++i) {
                    unsigned long long aa = pack2(a[i], a[i]);
                    fma2(acc[i][0], aa, bb[0]);
                    fma2(acc[i][1], aa, bb[1]);
                    fma2(acc[i][2], aa, bb[2]);
                    fma2(acc[i][3], aa, bb[3]);
                }
            }
            __syncthreads();
        }

        // b1 folded here (kh' = k@W1b + b1)
        float4 bv0 = *(const float4*)&b1[bn0 + 4 * tx];
        float4 bv1 = *(const float4*)&b1[bn0 + 64 + 4 * tx];

#pragma unroll
        for (int i = 0; i < 4; ++i) {
            int row = bm0 + 4 * ty + i;
            float2 p0 = unpack2(acc[i][0]);
            float2 p1 = unpack2(acc[i][1]);
            float2 p2 = unpack2(acc[i][2]);
            float2 p3 = unpack2(acc[i][3]);
            *(float4*)&g_kh[(size_t)row * Hh + bn0 + 4 * tx] =
                make_float4(p0.x + bv0.x, p0.y + bv0.y, p1.x + bv0.z, p1.y + bv0.w);
            *(float4*)&g_kh[(size_t)row * Hh + bn0 + 64 + 4 * tx] =
                make_float4(p2.x + bv1.x, p2.y + bv1.y, p3.x + bv1.z, p3.y + bv1.w);
        }
    } else {
        // ------------------- qh role: 4 b x 256 h per block --------------------
        int r  = blockIdx.x - 256;       // 0..31
        int hc = r & 1;                  // h chunk (2 x 256)
        int bg = r >> 1;                 // b group (16 x 4)
        int h  = hc * 256 + t;
        int b0 = bg * 4;

        int bi   = t >> 6;               // 0..3
        int lane = t & 63;               // 0..63
        const float* qrow = qemb + (size_t)Xq[b0 + bi] * Dd;
#pragma unroll
        for (int j = 0; j < 8; ++j) {
            int d = lane + 64 * j;
            sm.qs[d][bi] = qrow[d];
        }
        __syncthreads();

        const float* w = W1 + h;         // W1[d][h], d in [0, D)
        unsigned long long acc01 = 0ULL, acc23 = 0ULL;
#pragma unroll 8
        for (int d = 0; d < Dd; ++d) {
            float wv = w[(size_t)d * Hh];
            float4 q4 = *(const float4*)&sm.qs[d][0];
            unsigned long long ws = pack2(wv, wv);
            fma2(acc01, pack2(q4.x, q4.y), ws);
            fma2(acc23, pack2(q4.z, q4.w), ws);
        }

        float2 p01 = unpack2(acc01);
        float2 p23 = unpack2(acc23);
        g_qh[(b0 + 0) * Hh + h] = p01.x;
        g_qh[(b0 + 1) * Hh + h] = p01.y;
        g_qh[(b0 + 2) * Hh + h] = p23.x;
        g_qh[(b0 + 3) * Hh + h] = p23.y;
    }
}

// ---------------------------------------------------------------------------
// Logits: logits[b][k] = sum_h relu(qh[b][h] + kh'[k][h]) * w2[h] + b2
// Packed exact relu: t = s + |s| = 2*relu(s), with w/2 pre-folded.
// Tile: 16 b x 32 k, 128 threads, grid 512 (128 k-blocks x 4 b-blocks).
// Per thread: 1 b x 2 k-pairs (4 outputs).
// ---------------------------------------------------------------------------
#define CK 32
#define CB 16
#define CH 32

__global__ __launch_bounds__(128) void logits_kernel(const float* __restrict__ W2,
                                                     const float* __restrict__ b2,
                                                     float* __restrict__ out) {
    __shared__ float qs[CH][17];                 // [h][b], pitch 17 (gcd 32 = 1)
    __shared__ float ks[CH][34];                 // [h][k], even pitch for LDS.64
    __shared__ unsigned long long w2p[CH];       // packed (w/2, w/2)

    const unsigned long long ABSM = 0x7FFFFFFF7FFFFFFFULL;

    int t   = threadIdx.x;
    int tkp = t & 7;                   // k-pairs at 2*tkp, 2*tkp+16
    int tb  = t >> 3;                  // b (16)
    int k0  = (blockIdx.x & 127) * CK;
    int b0  = (blockIdx.x >> 7) * CB;

    unsigned long long acc0 = 0ULL, acc1 = 0ULL;

    for (int h0 = 0; h0 < Hh; h0 += CH) {
        // qh tile: 16 b x 32 h, transposed (512 elems / 128 thr = 4)
#pragma unroll
        for (int i = 0; i < 4; ++i) {
            int lin = t + i * 128;               // 0..511
            int b = lin >> 5, hh = lin & 31;
            qs[hh][b] = g_qh[(b0 + b) * Hh + h0 + hh];
        }
        // kh tile: 32 k x 32 h, transposed (1024 elems / 128 thr = 8)
#pragma unroll
        for (int i = 0; i < 8; ++i) {
            int lin = t + i * 128;               // 0..1023
            int k = lin >> 5, hh = lin & 31;
            ks[hh][k] = g_kh[(size_t)(k0 + k) * Hh + h0 + hh];
        }
        if (t < CH) {
            float wv = W2[h0 + t] * 0.5f;
            w2p[t] = pack2(wv, wv);
        }
        __syncthreads();

#pragma unroll 8
        for (int hh = 0; hh < CH; ++hh) {
            unsigned long long w2  = w2p[hh];
            unsigned long long kk0 = *(const unsigned long long*)&ks[hh][2 * tkp];
            unsigned long long kk1 = *(const unsigned long long*)&ks[hh][2 * tkp + 16];
            float qv = qs[hh][tb];
            unsigned long long qq = pack2(qv, qv);
            unsigned long long s0 = add2(qq, kk0);
            unsigned long long s1 = add2(qq, kk1);
            s0 = add2(s0, s0 & ABSM);            // = 2*relu, exact
            s1 = add2(s1, s1 & ABSM);
            fma2(acc0, s0, w2);
            fma2(acc1, s1, w2);
        }
        __syncthreads();
    }

    float bias = b2[0];
    int b = b0 + tb;
    float2 r0 = unpack2(acc0);
    float2 r1 = unpack2(acc1);
    *(float2*)&out[(size_t)b * Kk + k0 + 2 * tkp] =
        make_float2(r0.x + bias, r0.y + bias);
    *(float2*)&out[(size_t)b * Kk + k0 + 2 * tkp + 16] =
        make_float2(r1.x + bias, r1.y + bias);
}

// ---------------------------------------------------------------------------
// Inputs (metadata order): X_query(int32, 64), query_embed(f32, 8192x512),
// key_embed(f32, 4096x512), W1(f32, 1024x512), b1(f32, 512),
// W2(f32, 512x1), b2(f32, 1). Output: f32, 64x4096.
// ---------------------------------------------------------------------------
extern "C" void kernel_launch(void* const* d_in, const int* in_sizes, int n_in,
                              void* d_out, int out_size) {
    const int*   Xq   = (const int*)d_in[0];
    const float* qemb = (const float*)d_in[1];
    const float* kemb = (const float*)d_in[2];
    const float* W1   = (const float*)d_in[3];
    const float* b1   = (const float*)d_in[4];
    const float* W2   = (const float*)d_in[5];
    const float* b2   = (const float*)d_in[6];
    float* out = (float*)d_out;

    // fused qh + kh (qh blocks hide under kh's tail wave)
    fused_qh_kh<<<288, 256>>>(Xq, qemb, kemb, W1, b1);

    // fused relu-broadcast-reduce, 512 blocks for occupancy
    logits_kernel<<<512, 128>>>(W2, b2, out);
}

// round 8
// speedup vs baseline: 1.0057x; 1.0057x over previous
#include <cuda_runtime.h>
#include <cuda_bf16.h>
#include <cstdint>

// Problem constants
#define Bq   64
#define Kk   4096
#define Dd   512
#define Hh   512

// Scratch (no cudaMalloc allowed)
__device__ float g_qh[Bq * Hh];
__device__ float g_kh[Kk * Hh];
__device__ float g_part[4 * Bq * Kk];                    // 4 h-quarter partials
__device__ __align__(16) __nv_bfloat16 g_Ah[Kk * Dd];    // key hi
__device__ __align__(16) __nv_bfloat16 g_Al[Kk * Dd];    // key lo
__device__ __align__(16) __nv_bfloat16 g_Bth[Hh * Dd];   // W1b^T hi  [n][k]
__device__ __align__(16) __nv_bfloat16 g_Btl[Hh * Dd];   // W1b^T lo  [n][k]

// ---------------------------------------------------------------------------
// f32x2 packed helpers
// ---------------------------------------------------------------------------
__device__ __forceinline__ unsigned long long pack2(float x, float y) {
    unsigned long long r;
    asm("mov.b64 %0, {%1, %2};" : "=l"(r) : "r"(__float_as_uint(x)), "r"(__float_as_uint(y)));
    return r;
}
__device__ __forceinline__ void fma2(unsigned long long& d,
                                     unsigned long long a, unsigned long long b) {
    asm("fma.rn.f32x2 %0, %1, %2, %0;" : "+l"(d) : "l"(a), "l"(b));
}
__device__ __forceinline__ unsigned long long add2(unsigned long long a,
                                                   unsigned long long b) {
    unsigned long long r;
    asm("add.rn.f32x2 %0, %1, %2;" : "=l"(r) : "l"(a), "l"(b));
    return r;
}
__device__ __forceinline__ float2 unpack2(unsigned long long v) {
    unsigned int lo, hi;
    asm("mov.b64 {%0, %1}, %2;" : "=r"(lo), "=r"(hi) : "l"(v));
    return make_float2(__uint_as_float(lo), __uint_as_float(hi));
}

// fp32 -> (hi, lo) bf16 split
__device__ __forceinline__ void split_bf16(float x, unsigned short& hi, unsigned short& lo) {
    __nv_bfloat16 h = __float2bfloat16_rn(x);
    float r = x - __bfloat162float(h);
    __nv_bfloat16 l = __float2bfloat16_rn(r);
    hi = __bfloat16_as_ushort(h);
    lo = __bfloat16_as_ushort(l);
}

__device__ __forceinline__ uint32_t smem_u32(const void* p) {
    uint32_t a;
    asm("{ .reg .u64 t; cvta.to.shared.u64 t, %1; cvt.u32.u64 %0, t; }" : "=r"(a) : "l"(p));
    return a;
}

// ---------------------------------------------------------------------------
// mma.sync helpers (sm_80 PTX — safe on the sm_100 ptxas target)
// ---------------------------------------------------------------------------
__device__ __forceinline__ void ldmx4(uint32_t* r, uint32_t addr) {
    asm volatile("ldmatrix.sync.aligned.m8n8.x4.shared.b16 {%0,%1,%2,%3}, [%4];"
        : "=r"(r[0]), "=r"(r[1]), "=r"(r[2]), "=r"(r[3]) : "r"(addr));
}
__device__ __forceinline__ void mma_bf16(float* c, const uint32_t* a, const uint32_t* b) {
    asm volatile("mma.sync.aligned.m16n8k16.row.col.f32.bf16.bf16.f32 "
        "{%0,%1,%2,%3}, {%4,%5,%6,%7}, {%8,%9}, {%0,%1,%2,%3};"
        : "+f"(c[0]), "+f"(c[1]), "+f"(c[2]), "+f"(c[3])
        : "r"(a[0]), "r"(a[1]), "r"(a[2]), "r"(a[3]), "r"(b[0]), "r"(b[1]));
}

// ---------------------------------------------------------------------------
// Kernel 1 (convert + qh), 3 roles by blockIdx:
//   [0,256)   : split key_embed -> g_Ah/g_Al (coalesced)
//   [256,512) : transpose+split W1[D:] -> g_Bth/g_Btl
//   [512,544) : qh = gather(query_embed) @ W1[:D]  (SIMT f32x2)
// ---------------------------------------------------------------------------
__global__ __launch_bounds__(256) void convert_kernel(const int* __restrict__ Xq,
                                                      const float* __restrict__ qemb,
                                                      const float* __restrict__ kemb,
                                                      const float* __restrict__ W1) {
    __shared__ union {
        float tr[32][33];
        float qs[Dd][4];
    } sm;
    int t = threadIdx.x;
    int bid = blockIdx.x;

    if (bid < 256) {
        // ---- role A: split key_embed (2M floats, 8192 per block) ----
#pragma unroll
        for (int j = 0; j < 8; ++j) {
            size_t i = (size_t)bid * 8192 + j * 1024 + t * 4;
            float4 v = *(const float4*)&kemb[i];
            unsigned short h0, l0, h1, l1, h2, l2, h3, l3;
            split_bf16(v.x, h0, l0); split_bf16(v.y, h1, l1);
            split_bf16(v.z, h2, l2); split_bf16(v.w, h3, l3);
            *(unsigned long long*)&g_Ah[i] =
                (unsigned long long)h0 | ((unsigned long long)h1 << 16) |
                ((unsigned long long)h2 << 32) | ((unsigned long long)h3 << 48);
            *(unsigned long long*)&g_Al[i] =
                (unsigned long long)l0 | ((unsigned long long)l1 << 16) |
                ((unsigned long long)l2 << 32) | ((unsigned long long)l3 << 48);
        }
    } else if (bid < 512) {
        // ---- role B: transpose+split W1b 32x32 tiles ----
        const float* W1b = W1 + (size_t)Dd * Hh;
        int tt = bid - 256;
        int kb = (tt >> 4) * 32;
        int nb = (tt & 15) * 32;
        int r  = t >> 3;
        int c4 = (t & 7) * 4;
        float4 v = *(const float4*)&W1b[(size_t)(kb + r) * Hh + nb + c4];
        sm.tr[r][c4 + 0] = v.x; sm.tr[r][c4 + 1] = v.y;
        sm.tr[r][c4 + 2] = v.z; sm.tr[r][c4 + 3] = v.w;
        __syncthreads();
        unsigned long long hv = 0, lv = 0;
#pragma unroll
        for (int j = 0; j < 4; ++j) {
            unsigned short h, l;
            split_bf16(sm.tr[c4 + j][r], h, l);
            hv |= (unsigned long long)h << (16 * j);
            lv |= (unsigned long long)l << (16 * j);
        }
        size_t o = (size_t)(nb + r) * Dd + kb + c4;
        *(unsigned long long*)&g_Bth[o] = hv;
        *(unsigned long long*)&g_Btl[o] = lv;
    } else {
        // ---- role qh: 4 b x 256 h per block (exact fp32) ----
        int r  = bid - 512;
        int hc = r & 1;
        int bg = r >> 1;
        int h  = hc * 256 + t;
        int b0 = bg * 4;

        int bi   = t >> 6;
        int lane64 = t & 63;
        const float* qrow = qemb + (size_t)Xq[b0 + bi] * Dd;
#pragma unroll
        for (int j = 0; j < 8; ++j) {
            int d = lane64 + 64 * j;
            sm.qs[d][bi] = qrow[d];
        }
        __syncthreads();

        const float* w = W1 + h;
        unsigned long long acc01 = 0ULL, acc23 = 0ULL;
#pragma unroll 8
        for (int d = 0; d < Dd; ++d) {
            float wv = w[(size_t)d * Hh];
            float4 q4 = *(const float4*)&sm.qs[d][0];
            unsigned long long ws = pack2(wv, wv);
            fma2(acc01, pack2(q4.x, q4.y), ws);
            fma2(acc23, pack2(q4.z, q4.w), ws);
        }
        float2 p01 = unpack2(acc01);
        float2 p23 = unpack2(acc23);
        g_qh[(b0 + 0) * Hh + h] = p01.x;
        g_qh[(b0 + 1) * Hh + h] = p01.y;
        g_qh[(b0 + 2) * Hh + h] = p23.x;
        g_qh[(b0 + 3) * Hh + h] = p23.y;
    }
}

// ---------------------------------------------------------------------------
// Kernel 2: kh' = key @ W1b + b1 via bf16 mma.sync, 3-term split:
//   seg0: Ah*Bh   seg1: Al*Bh   seg2: Ah*Bl    (residual Al*Bl ~ 2^-18)
// CTA tile 128x128, 8 warps (2m x 4n), warp tile 64x32 (4 m16 x 4 n8).
// Double-buffered smem, register-prefetched global loads.
// NOTE: smem STORES go through generic pointers (smbuf[]); the cvta.to.shared
// u32 addresses are used ONLY as ldmatrix operands (round-7 fix).
// ---------------------------------------------------------------------------
#define APITCH 24                    // bf16 pitch: 48B rows, conflict-free ldmatrix
#define BUFE   (128 * APITCH)        // elements per buffer (3072)
#define BUFB   (BUFE * 2)            // bytes per buffer (6144)

__global__ __launch_bounds__(256, 1) void kh_gemm(const float* __restrict__ b1) {
    __shared__ __nv_bfloat16 smbuf[4 * BUFE];   // A0 A1 B0 B1 = 24 KB

    int t    = threadIdx.x;
    int wid  = t >> 5;
    int lane = t & 31;
    int m0 = (blockIdx.x >> 2) * 128;
    int n0 = (blockIdx.x & 3) * 128;
    int wm0 = (wid & 1) * 64;
    int wn0 = (wid >> 1) * 32;

    uint32_t sbase = smem_u32(smbuf);
    uint32_t sA = sbase;                 // A buffers (ldmatrix operand space)
    uint32_t sB = sbase + 2 * BUFB;      // B buffers

    // ldmatrix per-lane byte offsets (within one buffer)
    uint32_t aoff[4], boff[2];
#pragma unroll
    for (int mt = 0; mt < 4; ++mt)
        aoff[mt] = ((wm0 + mt * 16 + (lane & 15)) * APITCH + (lane >> 4) * 8) * 2;
    {
        int quad = lane >> 3, l8 = lane & 7;
#pragma unroll
        for (int p = 0; p < 2; ++p)
            boff[p] = ((wn0 + 16 * p + (quad >> 1) * 8 + l8) * APITCH + (quad & 1) * 8) * 2;
    }

    // staging mapping: row = t>>1, half = (t&1)*8  (16B-aligned: 48*row + 16*half8)
    int srow = t >> 1;
    int shalf = (t & 1) * 8;
    __nv_bfloat16* stA = &smbuf[srow * APITCH + shalf];            // A0
    __nv_bfloat16* stB = &smbuf[2 * BUFE + srow * APITCH + shalf]; // B0

    float acc[4][4][4];
#pragma unroll
    for (int i = 0; i < 4; ++i)
#pragma unroll
        for (int j = 0; j < 4; ++j)
#pragma unroll
            for (int p = 0; p < 4; ++p) acc[i][j][p] = 0.f;

    const __nv_bfloat16* Aplane[3] = {g_Ah, g_Al, g_Ah};
    const __nv_bfloat16* Bplane[3] = {g_Bth, g_Bth, g_Btl};

    // preload step 0 into buffer 0
    uint4 aR = *(const uint4*)&g_Ah[(size_t)(m0 + srow) * Dd + shalf];
    uint4 bR = *(const uint4*)&g_Bth[(size_t)(n0 + srow) * Dd + shalf];
    *(uint4*)stA = aR;
    *(uint4*)stB = bR;
    __syncthreads();

    const int NSTEP = 96;            // 3 segments x 32 k16-steps
    for (int s = 0; s < NSTEP; ++s) {
        int cur = s & 1;

        // prefetch next step's tiles into registers
        if (s + 1 < NSTEP) {
            int seg = (s + 1) >> 5;
            int kk  = ((s + 1) & 31) << 4;
            aR = *(const uint4*)&Aplane[seg][(size_t)(m0 + srow) * Dd + kk + shalf];
            bR = *(const uint4*)&Bplane[seg][(size_t)(n0 + srow) * Dd + kk + shalf];
        }

        // compute from buffer cur (ldmatrix uses shared-space u32 addresses)
        uint32_t a[4][4], bfr[4][2];
        uint32_t cA = sA + cur * BUFB;
        uint32_t cB = sB + cur * BUFB;
#pragma unroll
        for (int mt = 0; mt < 4; ++mt) ldmx4(a[mt], cA + aoff[mt]);
#pragma unroll
        for (int p = 0; p < 2; ++p) {
            uint32_t r[4];
            ldmx4(r, cB + boff[p]);
            bfr[2 * p][0] = r[0]; bfr[2 * p][1] = r[1];
            bfr[2 * p + 1][0] = r[2]; bfr[2 * p + 1][1] = r[3];
        }
#pragma unroll
        for (int mt = 0; mt < 4; ++mt)
#pragma unroll
            for (int nt = 0; nt < 4; ++nt)
                mma_bf16(acc[mt][nt], a[mt], bfr[nt]);

        // stage next step into the other buffer (generic pointers)
        if (s + 1 < NSTEP) {
            int nxt = cur ^ 1;
            *(uint4*)(stA + nxt * BUFE) = aR;
            *(uint4*)(stB + nxt * BUFE) = bR;
        }
        __syncthreads();
    }

    // epilogue: + b1 -> g_kh
#pragma unroll
    for (int mt = 0; mt < 4; ++mt) {
        int rg = m0 + wm0 + mt * 16 + (lane >> 2);
#pragma unroll
        for (int nt = 0; nt < 4; ++nt) {
            int ng = n0 + wn0 + nt * 8 + (lane & 3) * 2;
            float2 bv = *(const float2*)&b1[ng];
            *(float2*)&g_kh[(size_t)rg * Hh + ng] =
                make_float2(acc[mt][nt][0] + bv.x, acc[mt][nt][1] + bv.y);
            *(float2*)&g_kh[(size_t)(rg + 8) * Hh + ng] =
                make_float2(acc[mt][nt][2] + bv.x, acc[mt][nt][3] + bv.y);
        }
    }
}

// ---------------------------------------------------------------------------
// Kernel 3: logits partials over h-quarters (128 h each).
// Tile 64k x 32b, 256 threads, thread = 4k x 2b. Exact packed relu
// (t = s + |s| = 2*relu(s)) with w/2 pre-folded. Grid 512.
// ---------------------------------------------------------------------------
#define CH 32

__global__ __launch_bounds__(256, 4) void logits_partial(const float* __restrict__ W2) {
    __shared__ float ks[CH][68];
    __shared__ unsigned long long qsp[CH][34];
    __shared__ unsigned long long w2p[CH];

    const unsigned long long ABSM = 0x7FFFFFFF7FFFFFFFULL;

    int t  = threadIdx.x;
    int tk = t & 15;
    int tb = t >> 4;
    int bx = blockIdx.x;
    int kt = bx & 63;
    int bt = (bx >> 6) & 1;
    int hq = bx >> 7;
    int k0 = kt * 64;
    int b0 = bt * 32;
    int hbase = hq * 128;

    unsigned long long acc[2][2] = {{0ULL, 0ULL}, {0ULL, 0ULL}};

    for (int cc = 0; cc < 4; ++cc) {
        int h0 = hbase + cc * CH;
#pragma unroll
        for (int i = 0; i < 8; ++i) {
            int lin = t + i * 256;
            int k = lin >> 5, hh = lin & 31;
            ks[hh][k] = g_kh[(size_t)(k0 + k) * Hh + h0 + hh];
        }
#pragma unroll
        for (int i = 0; i < 4; ++i) {
            int lin = t + i * 256;
            int b = lin >> 5, hh = lin & 31;
            float qv = g_qh[(b0 + b) * Hh + h0 + hh];
            qsp[hh][b] = pack2(qv, qv);
        }
        if (t < CH) {
            float wv = W2[h0 + t] * 0.5f;
            w2p[t] = pack2(wv, wv);
        }
        __syncthreads();

#pragma unroll 8
        for (int hh = 0; hh < CH; ++hh) {
            unsigned long long w2 = w2p[hh];
            unsigned long long kk0 = *(const unsigned long long*)&ks[hh][4 * tk];
            unsigned long long kk1 = *(const unsigned long long*)&ks[hh][4 * tk + 2];
            unsigned long long qq0 = qsp[hh][2 * tb];
            unsigned long long qq1 = qsp[hh][2 * tb + 1];
            unsigned long long s;
            s = add2(qq0, kk0); s = add2(s, s & ABSM); fma2(acc[0][0], s, w2);
            s = add2(qq0, kk1); s = add2(s, s & ABSM); fma2(acc[0][1], s, w2);
            s = add2(qq1, kk0); s = add2(s, s & ABSM); fma2(acc[1][0], s, w2);
            s = add2(qq1, kk1); s = add2(s, s & ABSM); fma2(acc[1][1], s, w2);
        }
        __syncthreads();
    }

    float* base = &g_part[(size_t)hq * Bq * Kk];
#pragma unroll
    for (int bi = 0; bi < 2; ++bi) {
        int b = b0 + 2 * tb + bi;
        float2 r0 = unpack2(acc[bi][0]);
        float2 r1 = unpack2(acc[bi][1]);
        *(float4*)&base[(size_t)b * Kk + k0 + 4 * tk] = make_float4(r0.x, r0.y, r1.x, r1.y);
    }
}

// ---------------------------------------------------------------------------
// Kernel 4: out = sum of 4 partials + b2
// ---------------------------------------------------------------------------
__global__ __launch_bounds__(256) void logits_reduce(const float* __restrict__ b2,
                                                     float* __restrict__ out) {
    int i = blockIdx.x * 256 + threadIdx.x;
    const float4* p0 = (const float4*)&g_part[0 * Bq * Kk];
    const float4* p1 = (const float4*)&g_part[1 * Bq * Kk];
    const float4* p2 = (const float4*)&g_part[2 * Bq * Kk];
    const float4* p3 = (const float4*)&g_part[3 * Bq * Kk];
    float bias = b2[0];
    float4 a = p0[i], b = p1[i], c = p2[i], d = p3[i];
    ((float4*)out)[i] = make_float4(a.x + b.x + c.x + d.x + bias,
                                    a.y + b.y + c.y + d.y + bias,
                                    a.z + b.z + c.z + d.z + bias,
                                    a.w + b.w + c.w + d.w + bias);
}

// ---------------------------------------------------------------------------
// Inputs (metadata order): X_query(int32, 64), query_embed(f32, 8192x512),
// key_embed(f32, 4096x512), W1(f32, 1024x512), b1(f32, 512),
// W2(f32, 512x1), b2(f32, 1). Output: f32, 64x4096.
// ---------------------------------------------------------------------------
extern "C" void kernel_launch(void* const* d_in, const int* in_sizes, int n_in,
                              void* d_out, int out_size) {
    const int*   Xq   = (const int*)d_in[0];
    const float* qemb = (const float*)d_in[1];
    const float* kemb = (const float*)d_in[2];
    const float* W1   = (const float*)d_in[3];
    const float* b1   = (const float*)d_in[4];
    const float* W2   = (const float*)d_in[5];
    const float* b2   = (const float*)d_in[6];
    float* out = (float*)d_out;

    convert_kernel<<<544, 256>>>(Xq, qemb, kemb, W1);   // split A/B + qh
    kh_gemm<<<128, 256>>>(b1);                          // tensor-core kh
    logits_partial<<<512, 256>>>(W2);                   // h-split relu-reduce
    logits_reduce<<<256, 256>>>(b2, out);               // combine + b2
}